// round 1
// baseline (speedup 1.0000x reference)
#include <cuda_runtime.h>

// D matrix: out = u^T D v, u from (x0,x1), v from (x2,x3), basis (1, cos, sin) per qubit.
// Stored row-padded [9][12] for float4 loads. Zero-initialized device global (pads stay 0).
__device__ float g_D[108];

// ---------------------------------------------------------------------------
// Prologue: build the fixed 16x16 unitary U from weights by simulating the
// circuit on all 16 basis states, form A = Re(U^T* Z0 U), then transform the
// half-angle quadratic form into the 9x9 full-angle bilinear form D.
// Launch: <<<1, 128>>>.
// ---------------------------------------------------------------------------
__global__ void qnn_prologue(const float* __restrict__ w) {
    __shared__ float Sr[16][16];   // Sr[col][i] = Re(U[i][col])
    __shared__ float Si[16][16];
    __shared__ float sA[16][16];

    const int tid = threadIdx.x;   // 0..127
    const int col = tid >> 3;      // which basis column this thread helps with
    const int p   = tid & 7;       // pair index within the column

    // init: column col = e_col
    Sr[col][p]     = (p == col) ? 1.f : 0.f;
    Sr[col][p + 8] = ((p + 8) == col) ? 1.f : 0.f;
    Si[col][p]     = 0.f;
    Si[col][p + 8] = 0.f;
    __syncthreads();

    // Circuit body: 2 layers of per-wire RX,RY,RZ then CNOT ring.
    // wire q <-> bit (3-q); flat index = q0*8 + q1*4 + q2*2 + q3.
    for (int layer = 0; layer < 2; ++layer) {
        for (int q = 0; q < 4; ++q) {
            const int stride = 8 >> q;
            const int i0 = ((p & ~(stride - 1)) << 1) | (p & (stride - 1));
            const int i1 = i0 + stride;
            for (int r = 0; r < 3; ++r) {
                float th = 0.5f * w[(layer * 4 + q) * 3 + r];
                float s, c;
                sincosf(th, &s, &c);
                float a0r = Sr[col][i0], a0i = Si[col][i0];
                float a1r = Sr[col][i1], a1i = Si[col][i1];
                float n0r, n0i, n1r, n1i;
                if (r == 0) {          // RX: [[c,-is],[-is,c]]
                    n0r =  c * a0r + s * a1i;   n0i =  c * a0i - s * a1r;
                    n1r =  s * a0i + c * a1r;   n1i = -s * a0r + c * a1i;
                } else if (r == 1) {   // RY: [[c,-s],[s,c]]
                    n0r =  c * a0r - s * a1r;   n0i =  c * a0i - s * a1i;
                    n1r =  s * a0r + c * a1r;   n1i =  s * a0i + c * a1i;
                } else {               // RZ: diag(e^{-i th}, e^{+i th})
                    n0r =  c * a0r + s * a0i;   n0i =  c * a0i - s * a0r;
                    n1r =  c * a1r - s * a1i;   n1i =  c * a1i + s * a1r;
                }
                Sr[col][i0] = n0r;  Si[col][i0] = n0i;
                Sr[col][i1] = n1r;  Si[col][i1] = n1i;
                __syncthreads();
            }
        }
        // CNOT ring: control->target wires (0,1),(1,2),(2,3),(3,0)
        const int cw[4] = {0, 1, 2, 3};
        const int tw[4] = {1, 2, 3, 0};
        for (int g = 0; g < 4; ++g) {
            const int bc = 3 - cw[g], bt = 3 - tw[g];
            if (p < 4) {
                int o0 = -1, o1 = -1;
                for (int b = 0; b < 4; ++b)
                    if (b != bc && b != bt) { if (o0 < 0) o0 = b; else o1 = b; }
                const int i = (1 << bc) | ((p & 1) << o0) | (((p >> 1) & 1) << o1);
                const int j = i | (1 << bt);
                float tr = Sr[col][i], ti = Si[col][i];
                Sr[col][i] = Sr[col][j];  Si[col][i] = Si[col][j];
                Sr[col][j] = tr;          Si[col][j] = ti;
            }
            __syncthreads();
        }
    }

    // A[j][l] = sum_i s_i * Re(conj(U[i][j]) U[i][l]),  s_i = +1 (i<8), -1 (i>=8)
    for (int e = tid; e < 256; e += 128) {
        const int j = e >> 4, l = e & 15;
        float acc = 0.f;
        for (int i = 0; i < 16; ++i) {
            const float sgn = (i < 8) ? 1.f : -1.f;
            acc += sgn * (Sr[j][i] * Sr[l][i] + Si[j][i] * Si[l][i]);
        }
        sA[j][l] = acc;
    }
    __syncthreads();

    // Transform A (half-angle product basis) -> D (full-angle (1,cos,sin) basis).
    // For each qubit: t=0: {(0,0):+,(1,1):+}/2, t=1: {(0,0):+,(1,1):-}/2, t=2: {(0,1):+,(1,0):+}/2
    if (tid < 108) {
        const int a = tid / 12, bb = tid % 12;
        float d = 0.f;
        if (bb < 9) {
            const int t[4] = { a / 3, a % 3, bb / 3, bb % 3 };
            for (int k = 0; k < 16; ++k) {
                int j = 0, l = 0;
                float sgn = 1.f;
                for (int qq = 0; qq < 4; ++qq) {
                    const int kk = (k >> qq) & 1;
                    int jq, lq;
                    if (t[qq] == 2) { jq = kk; lq = 1 - kk; }
                    else            { jq = kk; lq = kk; if (t[qq] == 1 && kk) sgn = -sgn; }
                    j |= jq << (3 - qq);
                    l |= lq << (3 - qq);
                }
                d += sgn * sA[j][l];
            }
            d *= 0.0625f;
        }
        g_D[tid] = d;
    }
}

// ---------------------------------------------------------------------------
// Main: one sample per thread. out = u^T D v.
// ---------------------------------------------------------------------------
__global__ void __launch_bounds__(256) qnn_main(const float4* __restrict__ x,
                                               float* __restrict__ out, int n) {
    __shared__ __align__(16) float sD[108];
    if (threadIdx.x < 27)
        ((float4*)sD)[threadIdx.x] = ((const float4*)g_D)[threadIdx.x];
    __syncthreads();

    const int idx = blockIdx.x * blockDim.x + threadIdx.x;
    if (idx >= n) return;

    const float4 xx = x[idx];
    float c0, s0, c1, s1, c2, s2, c3, s3;
    __sincosf(xx.x, &s0, &c0);
    __sincosf(xx.y, &s1, &c1);
    __sincosf(xx.z, &s2, &c2);
    __sincosf(xx.w, &s3, &c3);

    const float u[9] = {1.f, c1, s1, c0, c0 * c1, c0 * s1, s0, s0 * c1, s0 * s1};
    const float v[9] = {1.f, c3, s3, c2, c2 * c3, c2 * s3, s2, s2 * c3, s2 * s3};

    float acc = 0.f;
#pragma unroll
    for (int a = 0; a < 9; ++a) {
        const float* R = sD + a * 12;
        const float4 r0 = *(const float4*)(R);
        const float4 r1 = *(const float4*)(R + 4);
        const float  r8 = R[8];
        float dot = r0.x * v[0] + r0.y * v[1] + r0.z * v[2] + r0.w * v[3]
                  + r1.x * v[4] + r1.y * v[5] + r1.z * v[6] + r1.w * v[7]
                  + r8 * v[8];
        acc += u[a] * dot;
    }
    out[idx] = acc;
}

extern "C" void kernel_launch(void* const* d_in, const int* in_sizes, int n_in,
                              void* d_out, int out_size) {
    const float* x = (const float*)d_in[0];
    const float* w = (const float*)d_in[1];
    float* out = (float*)d_out;
    const int B = out_size;

    qnn_prologue<<<1, 128>>>(w);
    const int blocks = (B + 255) / 256;
    qnn_main<<<blocks, 256>>>((const float4*)x, out, B);
}

// round 2
// speedup vs baseline: 1.1432x; 1.1432x over previous
#include <cuda_runtime.h>

// Packed D matrix: out = u^T D v; each element stored duplicated as (d,d) in a
// 64-bit word for fma.rn.f32x2. Rows padded to 10 u64 (80B) so every row start
// is 16B-aligned for vector constant loads.
__device__ unsigned long long g_Dp[90];
__constant__ __align__(16) unsigned long long cDp[90];

__device__ __forceinline__ unsigned long long pack2(float lo, float hi) {
    unsigned long long r;
    asm("mov.b64 %0, {%1, %2};" : "=l"(r) : "f"(lo), "f"(hi));
    return r;
}
__device__ __forceinline__ unsigned long long mul2(unsigned long long a, unsigned long long b) {
    unsigned long long d;
    asm("mul.rn.f32x2 %0, %1, %2;" : "=l"(d) : "l"(a), "l"(b));
    return d;
}
__device__ __forceinline__ unsigned long long fma2(unsigned long long a, unsigned long long b,
                                                   unsigned long long c) {
    unsigned long long d;
    asm("fma.rn.f32x2 %0, %1, %2, %3;" : "=l"(d) : "l"(a), "l"(b), "l"(c));
    return d;
}

// ---------------------------------------------------------------------------
// Prologue: build U (16x16) by evolving all 16 basis columns, form
// A = Re(U^dag Z0 U), transform to the 9x9 full-angle bilinear form D, pack.
// Fused gates: G = RZ(c)RY(b)RX(a) is SU(2): [[alpha, -conj(beta)],[beta, conj(alpha)]]
//   alpha = (cc*cb*ca + sc*sb*sa) + i(cc*sb*sa - sc*cb*ca)
//   beta  = (cc*sb*ca + sc*cb*sa) + i(sc*sb*ca - cc*cb*sa)
// Launch: <<<1, 128>>>.
// ---------------------------------------------------------------------------
__global__ void qnn_prologue(const float* __restrict__ w) {
    __shared__ float Sr[16][16];   // Sr[col][i] = Re(U[i][col])
    __shared__ float Si[16][16];
    __shared__ float sA[16][16];
    __shared__ float Gs[8][4];     // {ar, ai, br, bi} per (layer,wire)

    const int tid = threadIdx.x;   // 0..127
    const int col = tid >> 3;
    const int p   = tid & 7;

    // init columns
    Sr[col][p]     = (p == col) ? 1.f : 0.f;
    Sr[col][p + 8] = ((p + 8) == col) ? 1.f : 0.f;
    Si[col][p]     = 0.f;
    Si[col][p + 8] = 0.f;

    // 8 fused gates computed in parallel by threads 0..7
    if (tid < 8) {
        float sa, ca, sb, cb, sc, cc;
        __sincosf(0.5f * w[3 * tid + 0], &sa, &ca);
        __sincosf(0.5f * w[3 * tid + 1], &sb, &cb);
        __sincosf(0.5f * w[3 * tid + 2], &sc, &cc);
        const float cbca = cb * ca, sbsa = sb * sa, sbca = sb * ca, cbsa = cb * sa;
        Gs[tid][0] = cc * cbca + sc * sbsa;   // ar
        Gs[tid][1] = cc * sbsa - sc * cbca;   // ai
        Gs[tid][2] = cc * sbca + sc * cbsa;   // br
        Gs[tid][3] = sc * sbca - cc * cbsa;   // bi
    }
    __syncthreads();

    // wire q <-> bit (3-q)
    for (int g = 0; g < 8; ++g) {
        const int q = g & 3;
        const int stride = 8 >> q;
        const int i0 = ((p & ~(stride - 1)) << 1) | (p & (stride - 1));
        const int i1 = i0 + stride;
        const float ar = Gs[g][0], ai = Gs[g][1], br = Gs[g][2], bi = Gs[g][3];
        const float a0r = Sr[col][i0], a0i = Si[col][i0];
        const float a1r = Sr[col][i1], a1i = Si[col][i1];
        // new0 = alpha*a0 - conj(beta)*a1 ; new1 = beta*a0 + conj(alpha)*a1
        Sr[col][i0] = ar * a0r - ai * a0i - br * a1r - bi * a1i;
        Si[col][i0] = ar * a0i + ai * a0r - br * a1i + bi * a1r;
        Sr[col][i1] = br * a0r - bi * a0i + ar * a1r + ai * a1i;
        Si[col][i1] = br * a0i + bi * a0r + ar * a1i - ai * a1r;
        __syncthreads();

        if (q == 3) {
            // CNOT ring: (0->1),(1->2),(2->3),(3->0)
            const int cw[4] = {0, 1, 2, 3};
            const int tw[4] = {1, 2, 3, 0};
            for (int k = 0; k < 4; ++k) {
                const int bc = 3 - cw[k], bt = 3 - tw[k];
                if (p < 4) {
                    int o0 = -1, o1 = -1;
                    for (int b = 0; b < 4; ++b)
                        if (b != bc && b != bt) { if (o0 < 0) o0 = b; else o1 = b; }
                    const int i = (1 << bc) | ((p & 1) << o0) | (((p >> 1) & 1) << o1);
                    const int j = i | (1 << bt);
                    float tr = Sr[col][i], ti = Si[col][i];
                    Sr[col][i] = Sr[col][j];  Si[col][i] = Si[col][j];
                    Sr[col][j] = tr;          Si[col][j] = ti;
                }
                __syncthreads();
            }
        }
    }

    // A[j][l] = sum_i sgn_i * Re(conj(U[i][j]) U[i][l]), sgn = +1 (i<8), -1 (i>=8)
    for (int e = tid; e < 256; e += 128) {
        const int j = e >> 4, l = e & 15;
        float acc = 0.f;
        for (int i = 0; i < 16; ++i) {
            const float sgn = (i < 8) ? 1.f : -1.f;
            acc += sgn * (Sr[j][i] * Sr[l][i] + Si[j][i] * Si[l][i]);
        }
        sA[j][l] = acc;
    }
    __syncthreads();

    // Half-angle product basis -> full-angle (1,cos,sin) basis; pack (d,d).
    if (tid < 90) {
        const int a = tid / 10, b = tid % 10;
        float d = 0.f;
        if (b < 9) {
            const int t[4] = { a / 3, a % 3, b / 3, b % 3 };
            for (int k = 0; k < 16; ++k) {
                int j = 0, l = 0;
                float sgn = 1.f;
                for (int qq = 0; qq < 4; ++qq) {
                    const int kk = (k >> qq) & 1;
                    int jq, lq;
                    if (t[qq] == 2) { jq = kk; lq = 1 - kk; }
                    else            { jq = kk; lq = kk; if (t[qq] == 1 && kk) sgn = -sgn; }
                    j |= jq << (3 - qq);
                    l |= lq << (3 - qq);
                }
                d += sgn * sA[j][l];
            }
            d *= 0.0625f;
        }
        g_Dp[tid] = pack2(d, d);
    }
}

// ---------------------------------------------------------------------------
// Main: two samples per thread, packed fp32x2 math, D from constant memory.
// ---------------------------------------------------------------------------
__global__ void __launch_bounds__(256) qnn_main(const float4* __restrict__ x4,
                                               float2* __restrict__ out, int npairs) {
    const int idx = blockIdx.x * blockDim.x + threadIdx.x;
    if (idx >= npairs) return;

    const float4 xa = x4[2 * idx];
    const float4 xb = x4[2 * idx + 1];

    float c0a, s0a, c1a, s1a, c2a, s2a, c3a, s3a;
    float c0b, s0b, c1b, s1b, c2b, s2b, c3b, s3b;
    __sincosf(xa.x, &s0a, &c0a);  __sincosf(xa.y, &s1a, &c1a);
    __sincosf(xa.z, &s2a, &c2a);  __sincosf(xa.w, &s3a, &c3a);
    __sincosf(xb.x, &s0b, &c0b);  __sincosf(xb.y, &s1b, &c1b);
    __sincosf(xb.z, &s2b, &c2b);  __sincosf(xb.w, &s3b, &c3b);

    const unsigned long long pc0 = pack2(c0a, c0b), ps0 = pack2(s0a, s0b);
    const unsigned long long pc1 = pack2(c1a, c1b), ps1 = pack2(s1a, s1b);
    const unsigned long long pc2 = pack2(c2a, c2b), ps2 = pack2(s2a, s2b);
    const unsigned long long pc3 = pack2(c3a, c3b), ps3 = pack2(s3a, s3b);

    // v[0]=1 implicit; v[1..8] = {c3, s3, c2, c2c3, c2s3, s2, s2c3, s2s3}
    unsigned long long pv[9];
    pv[1] = pc3;             pv[2] = ps3;
    pv[3] = pc2;             pv[4] = mul2(pc2, pc3);
    pv[5] = mul2(pc2, ps3);  pv[6] = ps2;
    pv[7] = mul2(ps2, pc3);  pv[8] = mul2(ps2, ps3);
    // u[0]=1 implicit; u[1..8] = {c1, s1, c0, c0c1, c0s1, s0, s0c1, s0s1}
    unsigned long long pu[9];
    pu[1] = pc1;             pu[2] = ps1;
    pu[3] = pc0;             pu[4] = mul2(pc0, pc1);
    pu[5] = mul2(pc0, ps1);  pu[6] = ps0;
    pu[7] = mul2(ps0, pc1);  pu[8] = mul2(ps0, ps1);

    unsigned long long acc = 0;
#pragma unroll
    for (int a = 0; a < 9; ++a) {
        const ulonglong2* row = reinterpret_cast<const ulonglong2*>(cDp + a * 10);
        const ulonglong2 r0 = row[0], r1 = row[1], r2 = row[2], r3 = row[3];
        const unsigned long long d8 = cDp[a * 10 + 8];
        unsigned long long dot = r0.x;                 // * v[0] == 1
        dot = fma2(r0.y, pv[1], dot);
        dot = fma2(r1.x, pv[2], dot);
        dot = fma2(r1.y, pv[3], dot);
        dot = fma2(r2.x, pv[4], dot);
        dot = fma2(r2.y, pv[5], dot);
        dot = fma2(r3.x, pv[6], dot);
        dot = fma2(r3.y, pv[7], dot);
        dot = fma2(d8,   pv[8], dot);
        if (a == 0) acc = dot;                          // * u[0] == 1
        else        acc = fma2(pu[a], dot, acc);
    }

    float lo, hi;
    asm("mov.b64 {%0, %1}, %2;" : "=f"(lo), "=f"(hi) : "l"(acc));
    out[idx] = make_float2(lo, hi);
}

extern "C" void kernel_launch(void* const* d_in, const int* in_sizes, int n_in,
                              void* d_out, int out_size) {
    const float* x = (const float*)d_in[0];
    const float* w = (const float*)d_in[1];
    float2* out = (float2*)d_out;
    const int B = out_size;
    const int npairs = B >> 1;

    qnn_prologue<<<1, 128>>>(w);

    void* dp_src = nullptr;
    cudaGetSymbolAddress(&dp_src, g_Dp);
    cudaMemcpyToSymbolAsync(cDp, dp_src, sizeof(g_Dp), 0,
                            cudaMemcpyDeviceToDevice, 0);

    const int blocks = (npairs + 255) / 256;
    qnn_main<<<blocks, 256>>>((const float4*)x, out, npairs);
}